// round 8
// baseline (speedup 1.0000x reference)
#include <cuda_runtime.h>
#include <cuda_bf16.h>
#include <cuda_fp16.h>
#include <cstdint>

#define D 128
#define MAXN 100000
#define MAXE 400000
#define TILE_M 64
#define NB256 391            // (MAXN+255)/256

// ---------------- scratch (allocation-free: device globals) ----------------
__device__ float g_stats[2 * D];                    // col sums / sumsq
__device__ float g_ab[2 * D];                       // BN affine a / b
__device__ unsigned short g_Whi[D * 136];           // bf16 hi, padded [n][k] stride 136
__device__ unsigned short g_Wlo[D * 136];           // bf16 lo
__device__ float g_h[(size_t)MAXN * D];             // h fp32 (51.2 MB) — self term
__device__ __half g_hh[(size_t)MAXN * D];           // h fp16 (25.6 MB) — gather copy
__device__ int   g_deg[MAXN];
__device__ int   g_off[MAXN];
__device__ int   g_cur[MAXN];
__device__ int   g_total;
__device__ int   g_ecol[MAXE];
__device__ float g_ewt[MAXE];

// ---------------- helpers ----------------
__device__ __forceinline__ uint32_t smem_u32(const void* p) {
    uint32_t a;
    asm("{ .reg .u64 t; cvta.to.shared.u64 t, %1; cvt.u32.u64 %0, t; }" : "=r"(a) : "l"(p));
    return a;
}
__device__ __forceinline__ void ldmx4(uint32_t addr, uint32_t r[4]) {
    asm volatile("ldmatrix.sync.aligned.m8n8.x4.shared.b16 {%0,%1,%2,%3}, [%4];"
                 : "=r"(r[0]), "=r"(r[1]), "=r"(r[2]), "=r"(r[3]) : "r"(addr));
}
__device__ __forceinline__ void mma16816(float c[4], const uint32_t a[4], const uint32_t b[2]) {
    asm volatile("mma.sync.aligned.m16n8k16.row.col.f32.bf16.bf16.f32 "
                 "{%0,%1,%2,%3}, {%4,%5,%6,%7}, {%8,%9}, {%0,%1,%2,%3};"
                 : "+f"(c[0]), "+f"(c[1]), "+f"(c[2]), "+f"(c[3])
                 : "r"(a[0]), "r"(a[1]), "r"(a[2]), "r"(a[3]), "r"(b[0]), "r"(b[1]));
}
__device__ __forceinline__ uint32_t pkbf2(float x, float y) {
    __nv_bfloat162 t = __floats2bfloat162_rn(x, y);
    return *(uint32_t*)&t;
}

// ---------------- k0a: zero CSR + stats scratch ----------------
__global__ void k0a_zero() {
    int i = blockIdx.x * 256 + threadIdx.x;
    if (i == 0) g_total = 0;
    if (i < 2 * D) g_stats[i] = 0.0f;
    if (i < MAXN) g_deg[i] = 0;
}
// ---------------- k0b: build padded W bf16 hi/lo ----------------
__global__ void k0b_wprep(const float* __restrict__ W) {
    int i = blockIdx.x * 256 + threadIdx.x;
    if (i < D * D) {
        int n = i >> 7, k = i & 127;
        float w = W[i];
        __nv_bfloat16 hi = __float2bfloat16(w);
        float lf = w - __bfloat162float(hi);
        g_Whi[n * 136 + k] = __bfloat16_as_ushort(hi);
        g_Wlo[n * 136 + k] = __bfloat16_as_ushort(__float2bfloat16(lf));
    }
}

// ---------------- k1: column sums / sumsq ----------------
__global__ void __launch_bounds__(256) k1_stats(const float4* __restrict__ x4, int nrows) {
    int tx = threadIdx.x & 31, ty = threadIdx.x >> 5;
    float4 s = {0.f, 0.f, 0.f, 0.f}, q = {0.f, 0.f, 0.f, 0.f};
    for (int r = blockIdx.x * 8 + ty; r < nrows; r += gridDim.x * 8) {
        float4 v = x4[(size_t)r * 32 + tx];
        s.x += v.x; s.y += v.y; s.z += v.z; s.w += v.w;
        q.x += v.x * v.x; q.y += v.y * v.y; q.z += v.z * v.z; q.w += v.w * v.w;
    }
    __shared__ float4 rs[8][32], rq[8][32];
    rs[ty][tx] = s; rq[ty][tx] = q;
    __syncthreads();
    if (ty == 0) {
        for (int w = 1; w < 8; w++) {
            float4 a = rs[w][tx], b = rq[w][tx];
            s.x += a.x; s.y += a.y; s.z += a.z; s.w += a.w;
            q.x += b.x; q.y += b.y; q.z += b.z; q.w += b.w;
        }
        atomicAdd(&g_stats[4 * tx + 0], s.x);
        atomicAdd(&g_stats[4 * tx + 1], s.y);
        atomicAdd(&g_stats[4 * tx + 2], s.z);
        atomicAdd(&g_stats[4 * tx + 3], s.w);
        atomicAdd(&g_stats[D + 4 * tx + 0], q.x);
        atomicAdd(&g_stats[D + 4 * tx + 1], q.y);
        atomicAdd(&g_stats[D + 4 * tx + 2], q.z);
        atomicAdd(&g_stats[D + 4 * tx + 3], q.w);
    }
}

// ---------------- k2: finalize BN affine ----------------
__global__ void k2_final(const float* __restrict__ gamma, const float* __restrict__ beta, float inv_n) {
    int c = threadIdx.x;
    float mu  = g_stats[c] * inv_n;
    float var = fmaxf(g_stats[D + c] * inv_n - mu * mu, 0.0f);
    float a = gamma[c] * rsqrtf(var + 1e-5f);
    g_ab[c] = a;
    g_ab[D + c] = beta[c] - mu * a;
}

// ---------------- k3: HMMA bf16 2-split GEMM + register prefetch ----------------
#define SM_WHI 0
#define SM_WLO 34816
#define SM_XHI 69632
#define SM_XLO 87040
#define SM_TOTAL 104448
#define XSTR 272     // row stride bytes

__global__ void __launch_bounds__(256, 2) k3_mma(const float* __restrict__ x,
                                                 int nrows, int ntiles) {
    extern __shared__ __align__(16) char sm[];
    uint32_t smb = smem_u32(sm);
    int tid = threadIdx.x, wid = tid >> 5, lane = tid & 31;
    int warp_m = wid & 1;       // 2 m-blocks of 32 rows
    int warp_n = wid >> 1;      // 4 n-blocks of 32 cols

    {
        const uint4* hs = (const uint4*)g_Whi;
        const uint4* ls = (const uint4*)g_Wlo;
        uint4* hd = (uint4*)(sm + SM_WHI);
        uint4* ld = (uint4*)(sm + SM_WLO);
        for (int i = tid; i < 2176; i += 256) { hd[i] = hs[i]; ld[i] = ls[i]; }
    }

    int laneRowA = (lane & 7) + ((lane >> 3) & 1) * 8;
    int laneKA   = (lane >> 4) * 8;
    int laneRowB = (lane & 7) + ((lane >> 4) & 1) * 8;
    int laneKB   = ((lane >> 3) & 1) * 8;
    uint32_t aoff = (uint32_t)((warp_m * 32 + laneRowA) * XSTR + laneKA * 2);
    uint32_t boff = (uint32_t)((warp_n * 32 + laneRowB) * XSTR + laneKB * 2);
    uint32_t a_hi = smb + SM_XHI + aoff, a_lo = smb + SM_XLO + aoff;
    uint32_t b_hi = smb + SM_WHI + boff, b_lo = smb + SM_WLO + boff;

    const float4* x4 = (const float4*)x;
    int row_in = tid >> 5;
    int cq = tid & 31;
    // loop-invariant BN affine for this thread's column quad
    float4 aba = ((const float4*)g_ab)[cq];
    float4 abb = ((const float4*)g_ab)[32 + cq];

    float4 v[8];
    {
        int t0 = blockIdx.x;
        #pragma unroll
        for (int it = 0; it < 8; it++) {
            int gr = t0 * TILE_M + row_in + it * 8;
            v[it] = (t0 < ntiles && gr < nrows) ? x4[(size_t)gr * 32 + cq]
                                                : make_float4(0.f, 0.f, 0.f, 0.f);
        }
    }

    for (int t = blockIdx.x; t < ntiles; t += gridDim.x) {
        // ---- convert regs -> bf16 hi/lo -> STS ----
        #pragma unroll
        for (int it = 0; it < 8; it++) {
            int r = row_in + it * 8;
            float y0 = fmaxf(fmaf(aba.x, v[it].x, abb.x), 0.f);
            float y1 = fmaxf(fmaf(aba.y, v[it].y, abb.y), 0.f);
            float y2 = fmaxf(fmaf(aba.z, v[it].z, abb.z), 0.f);
            float y3 = fmaxf(fmaf(aba.w, v[it].w, abb.w), 0.f);
            __nv_bfloat16 h0 = __float2bfloat16(y0), h1 = __float2bfloat16(y1);
            __nv_bfloat16 h2 = __float2bfloat16(y2), h3 = __float2bfloat16(y3);
            uint2 hiw, low;
            hiw.x = (uint32_t)__bfloat16_as_ushort(h0) | ((uint32_t)__bfloat16_as_ushort(h1) << 16);
            hiw.y = (uint32_t)__bfloat16_as_ushort(h2) | ((uint32_t)__bfloat16_as_ushort(h3) << 16);
            low.x = pkbf2(y0 - __bfloat162float(h0), y1 - __bfloat162float(h1));
            low.y = pkbf2(y2 - __bfloat162float(h2), y3 - __bfloat162float(h3));
            uint32_t off = (uint32_t)(r * XSTR + cq * 8);
            *(uint2*)(sm + SM_XHI + off) = hiw;
            *(uint2*)(sm + SM_XLO + off) = low;
        }
        __syncthreads();

        // ---- issue prefetch of next tile ----
        {
            int tn = t + gridDim.x;
            #pragma unroll
            for (int it = 0; it < 8; it++) {
                int gr = tn * TILE_M + row_in + it * 8;
                if (tn < ntiles && gr < nrows) v[it] = x4[(size_t)gr * 32 + cq];
                else v[it] = make_float4(0.f, 0.f, 0.f, 0.f);
            }
        }

        // ---- mainloop ----
        float acc[2][4][4];
        #pragma unroll
        for (int mt = 0; mt < 2; mt++)
            #pragma unroll
            for (int nt = 0; nt < 4; nt++)
                #pragma unroll
                for (int j = 0; j < 4; j++) acc[mt][nt][j] = 0.f;

        for (int ko = 0; ko < 8; ko++) {
            uint32_t kb = ko * 32;
            uint32_t ah[2][4], al[2][4];
            #pragma unroll
            for (int mt = 0; mt < 2; mt++) {
                ldmx4(a_hi + mt * (16 * XSTR) + kb, ah[mt]);
                ldmx4(a_lo + mt * (16 * XSTR) + kb, al[mt]);
            }
            uint32_t bh[4][2], bl[4][2];
            #pragma unroll
            for (int np = 0; np < 2; np++) {
                uint32_t tm[4];
                ldmx4(b_hi + np * (16 * XSTR) + kb, tm);
                bh[2*np][0] = tm[0]; bh[2*np][1] = tm[1];
                bh[2*np+1][0] = tm[2]; bh[2*np+1][1] = tm[3];
                ldmx4(b_lo + np * (16 * XSTR) + kb, tm);
                bl[2*np][0] = tm[0]; bl[2*np][1] = tm[1];
                bl[2*np+1][0] = tm[2]; bl[2*np+1][1] = tm[3];
            }
            #pragma unroll
            for (int mt = 0; mt < 2; mt++)
                #pragma unroll
                for (int nt = 0; nt < 4; nt++) {
                    mma16816(acc[mt][nt], ah[mt], bh[nt]);
                    mma16816(acc[mt][nt], ah[mt], bl[nt]);
                    mma16816(acc[mt][nt], al[mt], bh[nt]);
                }
        }

        // ---- epilogue: write h fp32 + fp16 shadow ----
        int rbase = t * TILE_M + warp_m * 32 + (lane >> 2);
        int cbase = warp_n * 32 + 2 * (lane & 3);
        #pragma unroll
        for (int mt = 0; mt < 2; mt++) {
            #pragma unroll
            for (int nt = 0; nt < 4; nt++) {
                int r0 = rbase + mt * 16;
                int c = cbase + nt * 8;
                if (r0 < nrows) {
                    *(float2*)&g_h[(size_t)r0 * D + c] = make_float2(acc[mt][nt][0], acc[mt][nt][1]);
                    __half2 p = __floats2half2_rn(acc[mt][nt][0], acc[mt][nt][1]);
                    *(__half2*)&g_hh[(size_t)r0 * D + c] = p;
                }
                if (r0 + 8 < nrows) {
                    *(float2*)&g_h[(size_t)(r0 + 8) * D + c] = make_float2(acc[mt][nt][2], acc[mt][nt][3]);
                    __half2 p = __floats2half2_rn(acc[mt][nt][2], acc[mt][nt][3]);
                    *(__half2*)&g_hh[(size_t)(r0 + 8) * D + c] = p;
                }
            }
        }
        __syncthreads();
    }
}

// ---------------- CSR build ----------------
__global__ void __launch_bounds__(256) k4a_hist(const int* __restrict__ ei, int E) {
    int base = blockIdx.x * 1024 + threadIdx.x;
    #pragma unroll
    for (int j = 0; j < 4; j++) {
        int e = base + j * 256;
        if (e < E) atomicAdd(&g_deg[ei[e]], 1);
    }
}
__global__ void __launch_bounds__(256) k4b_off(int N) {
    int i = blockIdx.x * 256 + threadIdx.x;
    int lane = threadIdx.x & 31;
    int v = (i < N) ? g_deg[i] : 0;
    int incl = v;
    #pragma unroll
    for (int o = 1; o < 32; o <<= 1) {
        int t = __shfl_up_sync(0xFFFFFFFFu, incl, o);
        if (lane >= o) incl += t;
    }
    int wsum = __shfl_sync(0xFFFFFFFFu, incl, 31);
    int base = 0;
    if (lane == 0) base = atomicAdd(&g_total, wsum);
    base = __shfl_sync(0xFFFFFFFFu, base, 0);
    if (i < N) {
        int off = base + incl - v;
        g_off[i] = off;
        g_cur[i] = off;
    }
}
__global__ void __launch_bounds__(256) k4c_fill(const int* __restrict__ ei,
                                                const float* __restrict__ ew, int E) {
    int base = blockIdx.x * 1024 + threadIdx.x;
    int e0 = base, e1 = base + 256, e2 = base + 512, e3 = base + 768;
    int r0 = (e0 < E) ? ei[e0] : -1;
    int r1 = (e1 < E) ? ei[e1] : -1;
    int r2 = (e2 < E) ? ei[e2] : -1;
    int r3 = (e3 < E) ? ei[e3] : -1;
    int p0 = (r0 >= 0) ? atomicAdd(&g_cur[r0], 1) : 0;
    int p1 = (r1 >= 0) ? atomicAdd(&g_cur[r1], 1) : 0;
    int p2 = (r2 >= 0) ? atomicAdd(&g_cur[r2], 1) : 0;
    int p3 = (r3 >= 0) ? atomicAdd(&g_cur[r3], 1) : 0;
    if (r0 >= 0) { g_ecol[p0] = ei[E + e0]; g_ewt[p0] = ew[e0]; }
    if (r1 >= 0) { g_ecol[p1] = ei[E + e1]; g_ewt[p1] = ew[e1]; }
    if (r2 >= 0) { g_ecol[p2] = ei[E + e2]; g_ewt[p2] = ew[e2]; }
    if (r3 >= 0) { g_ecol[p3] = ei[E + e3]; g_ewt[p3] = ew[e3]; }
}

// ---------------- k5: per-node fp16 gather aggregate + fp32 h*h ----------------
__global__ void __launch_bounds__(256) k5_agg(float* __restrict__ out, int N) {
    int n = blockIdx.x * 8 + (threadIdx.x >> 5);
    if (n >= N) return;
    int lane = threadIdx.x & 31;
    int s = g_off[n];
    int e = s + g_deg[n];
    const uint2* hh = (const uint2*)g_hh;     // 8B = 4 halves per lane
    float4 acc = {0.f, 0.f, 0.f, 0.f};
    int j = s;
    for (; j + 4 <= e; j += 4) {
        int c0 = __ldg(&g_ecol[j]),     c1 = __ldg(&g_ecol[j + 1]);
        int c2 = __ldg(&g_ecol[j + 2]), c3 = __ldg(&g_ecol[j + 3]);
        float w0 = __ldg(&g_ewt[j]),     w1 = __ldg(&g_ewt[j + 1]);
        float w2 = __ldg(&g_ewt[j + 2]), w3 = __ldg(&g_ewt[j + 3]);
        uint2 p0 = hh[(size_t)c0 * 32 + lane];
        uint2 p1 = hh[(size_t)c1 * 32 + lane];
        uint2 p2 = hh[(size_t)c2 * 32 + lane];
        uint2 p3 = hh[(size_t)c3 * 32 + lane];
        float2 a0 = __half22float2(*(__half2*)&p0.x), b0 = __half22float2(*(__half2*)&p0.y);
        float2 a1 = __half22float2(*(__half2*)&p1.x), b1 = __half22float2(*(__half2*)&p1.y);
        float2 a2 = __half22float2(*(__half2*)&p2.x), b2 = __half22float2(*(__half2*)&p2.y);
        float2 a3 = __half22float2(*(__half2*)&p3.x), b3 = __half22float2(*(__half2*)&p3.y);
        acc.x = fmaf(w0, a0.x, acc.x); acc.y = fmaf(w0, a0.y, acc.y);
        acc.z = fmaf(w0, b0.x, acc.z); acc.w = fmaf(w0, b0.y, acc.w);
        acc.x = fmaf(w1, a1.x, acc.x); acc.y = fmaf(w1, a1.y, acc.y);
        acc.z = fmaf(w1, b1.x, acc.z); acc.w = fmaf(w1, b1.y, acc.w);
        acc.x = fmaf(w2, a2.x, acc.x); acc.y = fmaf(w2, a2.y, acc.y);
        acc.z = fmaf(w2, b2.x, acc.z); acc.w = fmaf(w2, b2.y, acc.w);
        acc.x = fmaf(w3, a3.x, acc.x); acc.y = fmaf(w3, a3.y, acc.y);
        acc.z = fmaf(w3, b3.x, acc.z); acc.w = fmaf(w3, b3.y, acc.w);
    }
    for (; j < e; j++) {
        int c0 = __ldg(&g_ecol[j]);
        float w0 = __ldg(&g_ewt[j]);
        uint2 p0 = hh[(size_t)c0 * 32 + lane];
        float2 a0 = __half22float2(*(__half2*)&p0.x), b0 = __half22float2(*(__half2*)&p0.y);
        acc.x = fmaf(w0, a0.x, acc.x); acc.y = fmaf(w0, a0.y, acc.y);
        acc.z = fmaf(w0, b0.x, acc.z); acc.w = fmaf(w0, b0.y, acc.w);
    }
    float4 hv = ((const float4*)g_h)[(size_t)n * 32 + lane];
    float4 o;
    o.x = fmaf(hv.x, hv.x, acc.x);
    o.y = fmaf(hv.y, hv.y, acc.y);
    o.z = fmaf(hv.z, hv.z, acc.z);
    o.w = fmaf(hv.w, hv.w, acc.w);
    __stcs(&((float4*)out)[(size_t)n * 32 + lane], o);
}

// ---------------- launch: fork CSR chain onto a side stream ----------------
extern "C" void kernel_launch(void* const* d_in, const int* in_sizes, int n_in,
                              void* d_out, int out_size) {
    const float* n_feat = (const float*)d_in[0];
    const int*   ei     = (const int*)d_in[1];
    const float* ew     = (const float*)d_in[2];
    const float* gamma  = (const float*)d_in[3];
    const float* beta   = (const float*)d_in[4];
    const float* W      = (const float*)d_in[5];
    float* out = (float*)d_out;

    int N = in_sizes[0] / D;
    int E = in_sizes[2];
    int ntiles = (N + TILE_M - 1) / TILE_M;

    cudaStream_t s2;
    cudaStreamCreateWithFlags(&s2, cudaStreamNonBlocking);
    cudaEvent_t ev_fork, ev_join;
    cudaEventCreateWithFlags(&ev_fork, cudaEventDisableTiming);
    cudaEventCreateWithFlags(&ev_join, cudaEventDisableTiming);

    k0a_zero<<<NB256, 256>>>();
    cudaEventRecord(ev_fork, 0);

    cudaStreamWaitEvent(s2, ev_fork, 0);
    k4a_hist<<<(E + 1023) / 1024, 256, 0, s2>>>(ei, E);
    k4b_off<<<(N + 255) / 256, 256, 0, s2>>>(N);
    k4c_fill<<<(E + 1023) / 1024, 256, 0, s2>>>(ei, ew, E);
    cudaEventRecord(ev_join, s2);

    k0b_wprep<<<64, 256>>>(W);
    k1_stats<<<264, 256>>>((const float4*)n_feat, N);
    k2_final<<<1, D>>>(gamma, beta, 1.0f / (float)N);
    cudaFuncSetAttribute(k3_mma, cudaFuncAttributeMaxDynamicSharedMemorySize, SM_TOTAL);
    k3_mma<<<296, 256, SM_TOTAL>>>(n_feat, N, ntiles);

    cudaStreamWaitEvent(0, ev_join, 0);
    k5_agg<<<(N + 7) / 8, 256>>>(out, N);

    cudaEventDestroy(ev_fork);
    cudaEventDestroy(ev_join);
    cudaStreamDestroy(s2);
}

// round 9
// speedup vs baseline: 1.0859x; 1.0859x over previous
#include <cuda_runtime.h>
#include <cuda_bf16.h>
#include <cstdint>

#define D 128
#define MAXN 100000
#define MAXE 400000
#define TILE_M 64
#define NB256 391            // (MAXN+255)/256

// ---------------- scratch (allocation-free: device globals) ----------------
__device__ float g_stats[2 * D];                    // col sums / sumsq
__device__ float g_ab[2 * D];                       // BN affine a / b
__device__ unsigned short g_Whi[D * 136];           // bf16 hi, padded [n][k] stride 136
__device__ unsigned short g_Wlo[D * 136];           // bf16 lo
__device__ float g_h[(size_t)MAXN * D];             // h (51.2 MB)
__device__ int   g_deg[MAXN];
__device__ int   g_off[MAXN];
__device__ int   g_cur[MAXN];
__device__ int   g_total;
__device__ int   g_tile3;                           // k3 work-stealing counter
__device__ int   g_ecol[MAXE];
__device__ float g_ewt[MAXE];

// ---------------- helpers ----------------
__device__ __forceinline__ uint32_t smem_u32(const void* p) {
    uint32_t a;
    asm("{ .reg .u64 t; cvta.to.shared.u64 t, %1; cvt.u32.u64 %0, t; }" : "=r"(a) : "l"(p));
    return a;
}
__device__ __forceinline__ void ldmx4(uint32_t addr, uint32_t r[4]) {
    asm volatile("ldmatrix.sync.aligned.m8n8.x4.shared.b16 {%0,%1,%2,%3}, [%4];"
                 : "=r"(r[0]), "=r"(r[1]), "=r"(r[2]), "=r"(r[3]) : "r"(addr));
}
__device__ __forceinline__ void mma16816(float c[4], const uint32_t a[4], const uint32_t b[2]) {
    asm volatile("mma.sync.aligned.m16n8k16.row.col.f32.bf16.bf16.f32 "
                 "{%0,%1,%2,%3}, {%4,%5,%6,%7}, {%8,%9}, {%0,%1,%2,%3};"
                 : "+f"(c[0]), "+f"(c[1]), "+f"(c[2]), "+f"(c[3])
                 : "r"(a[0]), "r"(a[1]), "r"(a[2]), "r"(a[3]), "r"(b[0]), "r"(b[1]));
}
__device__ __forceinline__ uint32_t pkbf2(float x, float y) {
    __nv_bfloat162 t = __floats2bfloat162_rn(x, y);
    return *(uint32_t*)&t;
}

// ---------------- k0a: zero CSR + stats scratch + tile counter ----------------
__global__ void k0a_zero() {
    int i = blockIdx.x * 256 + threadIdx.x;
    if (i == 0) { g_total = 0; g_tile3 = 0; }
    if (i < 2 * D) g_stats[i] = 0.0f;
    if (i < MAXN) g_deg[i] = 0;
}
// ---------------- k0b: build padded W bf16 hi/lo ----------------
__global__ void k0b_wprep(const float* __restrict__ W) {
    int i = blockIdx.x * 256 + threadIdx.x;
    if (i < D * D) {
        int n = i >> 7, k = i & 127;
        float w = W[i];
        __nv_bfloat16 hi = __float2bfloat16(w);
        float lf = w - __bfloat162float(hi);
        g_Whi[n * 136 + k] = __bfloat16_as_ushort(hi);
        g_Wlo[n * 136 + k] = __bfloat16_as_ushort(__float2bfloat16(lf));
    }
}

// ---------------- k1: column sums / sumsq ----------------
__global__ void __launch_bounds__(256) k1_stats(const float4* __restrict__ x4, int nrows) {
    int tx = threadIdx.x & 31, ty = threadIdx.x >> 5;
    float4 s = {0.f, 0.f, 0.f, 0.f}, q = {0.f, 0.f, 0.f, 0.f};
    for (int r = blockIdx.x * 8 + ty; r < nrows; r += gridDim.x * 8) {
        float4 v = x4[(size_t)r * 32 + tx];
        s.x += v.x; s.y += v.y; s.z += v.z; s.w += v.w;
        q.x += v.x * v.x; q.y += v.y * v.y; q.z += v.z * v.z; q.w += v.w * v.w;
    }
    __shared__ float4 rs[8][32], rq[8][32];
    rs[ty][tx] = s; rq[ty][tx] = q;
    __syncthreads();
    if (ty == 0) {
        for (int w = 1; w < 8; w++) {
            float4 a = rs[w][tx], b = rq[w][tx];
            s.x += a.x; s.y += a.y; s.z += a.z; s.w += a.w;
            q.x += b.x; q.y += b.y; q.z += b.z; q.w += b.w;
        }
        atomicAdd(&g_stats[4 * tx + 0], s.x);
        atomicAdd(&g_stats[4 * tx + 1], s.y);
        atomicAdd(&g_stats[4 * tx + 2], s.z);
        atomicAdd(&g_stats[4 * tx + 3], s.w);
        atomicAdd(&g_stats[D + 4 * tx + 0], q.x);
        atomicAdd(&g_stats[D + 4 * tx + 1], q.y);
        atomicAdd(&g_stats[D + 4 * tx + 2], q.z);
        atomicAdd(&g_stats[D + 4 * tx + 3], q.w);
    }
}

// ---------------- k2: finalize BN affine ----------------
__global__ void k2_final(const float* __restrict__ gamma, const float* __restrict__ beta, float inv_n) {
    int c = threadIdx.x;
    float mu  = g_stats[c] * inv_n;
    float var = fmaxf(g_stats[D + c] * inv_n - mu * mu, 0.0f);
    float a = gamma[c] * rsqrtf(var + 1e-5f);
    g_ab[c] = a;
    g_ab[D + c] = beta[c] - mu * a;
}

// ---------------- k3: HMMA bf16 2-split GEMM + prefetch + work stealing ----------------
#define SM_WHI 0
#define SM_WLO 34816
#define SM_XHI 69632
#define SM_XLO 87040
#define SM_TOTAL 104448
#define XSTR 272     // row stride bytes

__global__ void __launch_bounds__(256, 2) k3_mma(const float* __restrict__ x,
                                                 int nrows, int ntiles) {
    extern __shared__ __align__(16) char sm[];
    __shared__ int s_t;
    uint32_t smb = smem_u32(sm);
    int tid = threadIdx.x, wid = tid >> 5, lane = tid & 31;
    int warp_m = wid & 1;       // 2 m-blocks of 32 rows
    int warp_n = wid >> 1;      // 4 n-blocks of 32 cols

    {
        const uint4* hs = (const uint4*)g_Whi;
        const uint4* ls = (const uint4*)g_Wlo;
        uint4* hd = (uint4*)(sm + SM_WHI);
        uint4* ld = (uint4*)(sm + SM_WLO);
        for (int i = tid; i < 2176; i += 256) { hd[i] = hs[i]; ld[i] = ls[i]; }
    }

    int laneRowA = (lane & 7) + ((lane >> 3) & 1) * 8;
    int laneKA   = (lane >> 4) * 8;
    int laneRowB = (lane & 7) + ((lane >> 4) & 1) * 8;
    int laneKB   = ((lane >> 3) & 1) * 8;
    uint32_t aoff = (uint32_t)((warp_m * 32 + laneRowA) * XSTR + laneKA * 2);
    uint32_t boff = (uint32_t)((warp_n * 32 + laneRowB) * XSTR + laneKB * 2);
    uint32_t a_hi = smb + SM_XHI + aoff, a_lo = smb + SM_XLO + aoff;
    uint32_t b_hi = smb + SM_WHI + boff, b_lo = smb + SM_WLO + boff;

    const float4* x4 = (const float4*)x;
    int row_in = tid >> 5;
    int cq = tid & 31;
    float4 aba = ((const float4*)g_ab)[cq];
    float4 abb = ((const float4*)g_ab)[32 + cq];

    // grab first tile
    if (tid == 0) s_t = atomicAdd(&g_tile3, 1);
    __syncthreads();
    int t = s_t;
    float4 v[8];
    if (t < ntiles) {
        #pragma unroll
        for (int it = 0; it < 8; it++) {
            int gr = t * TILE_M + row_in + it * 8;
            v[it] = (gr < nrows) ? x4[(size_t)gr * 32 + cq] : make_float4(0.f, 0.f, 0.f, 0.f);
        }
    }

    while (t < ntiles) {
        // fetch next tile id early (latency hides under convert/STS)
        if (tid == 0) s_t = atomicAdd(&g_tile3, 1);

        // ---- convert regs -> bf16 hi/lo -> STS ----
        #pragma unroll
        for (int it = 0; it < 8; it++) {
            int r = row_in + it * 8;
            float y0 = fmaxf(fmaf(aba.x, v[it].x, abb.x), 0.f);
            float y1 = fmaxf(fmaf(aba.y, v[it].y, abb.y), 0.f);
            float y2 = fmaxf(fmaf(aba.z, v[it].z, abb.z), 0.f);
            float y3 = fmaxf(fmaf(aba.w, v[it].w, abb.w), 0.f);
            __nv_bfloat16 h0 = __float2bfloat16(y0), h1 = __float2bfloat16(y1);
            __nv_bfloat16 h2 = __float2bfloat16(y2), h3 = __float2bfloat16(y3);
            uint2 hiw, low;
            hiw.x = (uint32_t)__bfloat16_as_ushort(h0) | ((uint32_t)__bfloat16_as_ushort(h1) << 16);
            hiw.y = (uint32_t)__bfloat16_as_ushort(h2) | ((uint32_t)__bfloat16_as_ushort(h3) << 16);
            low.x = pkbf2(y0 - __bfloat162float(h0), y1 - __bfloat162float(h1));
            low.y = pkbf2(y2 - __bfloat162float(h2), y3 - __bfloat162float(h3));
            uint32_t off = (uint32_t)(r * XSTR + cq * 8);
            *(uint2*)(sm + SM_XHI + off) = hiw;
            *(uint2*)(sm + SM_XLO + off) = low;
        }
        __syncthreads();          // STS + s_t visible
        int t_next = s_t;

        // ---- prefetch next tile (hides under MMAs) ----
        if (t_next < ntiles) {
            #pragma unroll
            for (int it = 0; it < 8; it++) {
                int gr = t_next * TILE_M + row_in + it * 8;
                v[it] = (gr < nrows) ? x4[(size_t)gr * 32 + cq] : make_float4(0.f, 0.f, 0.f, 0.f);
            }
        }

        // ---- mainloop: 8 k16-steps x 3 products ----
        float acc[2][4][4];
        #pragma unroll
        for (int mt = 0; mt < 2; mt++)
            #pragma unroll
            for (int nt = 0; nt < 4; nt++)
                #pragma unroll
                for (int j = 0; j < 4; j++) acc[mt][nt][j] = 0.f;

        for (int ko = 0; ko < 8; ko++) {
            uint32_t kb = ko * 32;
            uint32_t ah[2][4], al[2][4];
            #pragma unroll
            for (int mt = 0; mt < 2; mt++) {
                ldmx4(a_hi + mt * (16 * XSTR) + kb, ah[mt]);
                ldmx4(a_lo + mt * (16 * XSTR) + kb, al[mt]);
            }
            uint32_t bh[4][2], bl[4][2];
            #pragma unroll
            for (int np = 0; np < 2; np++) {
                uint32_t tm[4];
                ldmx4(b_hi + np * (16 * XSTR) + kb, tm);
                bh[2*np][0] = tm[0]; bh[2*np][1] = tm[1];
                bh[2*np+1][0] = tm[2]; bh[2*np+1][1] = tm[3];
                ldmx4(b_lo + np * (16 * XSTR) + kb, tm);
                bl[2*np][0] = tm[0]; bl[2*np][1] = tm[1];
                bl[2*np+1][0] = tm[2]; bl[2*np+1][1] = tm[3];
            }
            #pragma unroll
            for (int mt = 0; mt < 2; mt++)
                #pragma unroll
                for (int nt = 0; nt < 4; nt++) {
                    mma16816(acc[mt][nt], ah[mt], bh[nt]);
                    mma16816(acc[mt][nt], ah[mt], bl[nt]);
                    mma16816(acc[mt][nt], al[mt], bh[nt]);
                }
        }

        // ---- epilogue: write h ----
        int rbase = t * TILE_M + warp_m * 32 + (lane >> 2);
        int cbase = warp_n * 32 + 2 * (lane & 3);
        #pragma unroll
        for (int mt = 0; mt < 2; mt++) {
            #pragma unroll
            for (int nt = 0; nt < 4; nt++) {
                int r0 = rbase + mt * 16;
                int c = cbase + nt * 8;
                if (r0 < nrows)
                    *(float2*)&g_h[(size_t)r0 * D + c] = make_float2(acc[mt][nt][0], acc[mt][nt][1]);
                if (r0 + 8 < nrows)
                    *(float2*)&g_h[(size_t)(r0 + 8) * D + c] = make_float2(acc[mt][nt][2], acc[mt][nt][3]);
            }
        }
        __syncthreads();          // protect smem X before next convert; s_t rewrite safe after this
        t = t_next;
    }
}

// ---------------- CSR build ----------------
__global__ void __launch_bounds__(256) k4a_hist(const int* __restrict__ ei, int E) {
    int base = blockIdx.x * 1024 + threadIdx.x;
    #pragma unroll
    for (int j = 0; j < 4; j++) {
        int e = base + j * 256;
        if (e < E) atomicAdd(&g_deg[ei[e]], 1);
    }
}
__global__ void __launch_bounds__(256) k4b_off(int N) {
    int i = blockIdx.x * 256 + threadIdx.x;
    int lane = threadIdx.x & 31;
    int v = (i < N) ? g_deg[i] : 0;
    int incl = v;
    #pragma unroll
    for (int o = 1; o < 32; o <<= 1) {
        int t = __shfl_up_sync(0xFFFFFFFFu, incl, o);
        if (lane >= o) incl += t;
    }
    int wsum = __shfl_sync(0xFFFFFFFFu, incl, 31);
    int base = 0;
    if (lane == 0) base = atomicAdd(&g_total, wsum);
    base = __shfl_sync(0xFFFFFFFFu, base, 0);
    if (i < N) {
        int off = base + incl - v;
        g_off[i] = off;
        g_cur[i] = off;
    }
}
__global__ void __launch_bounds__(256) k4c_fill(const int* __restrict__ ei,
                                                const float* __restrict__ ew, int E) {
    int base = blockIdx.x * 1024 + threadIdx.x;
    int e0 = base, e1 = base + 256, e2 = base + 512, e3 = base + 768;
    int r0 = (e0 < E) ? ei[e0] : -1;
    int r1 = (e1 < E) ? ei[e1] : -1;
    int r2 = (e2 < E) ? ei[e2] : -1;
    int r3 = (e3 < E) ? ei[e3] : -1;
    int p0 = (r0 >= 0) ? atomicAdd(&g_cur[r0], 1) : 0;
    int p1 = (r1 >= 0) ? atomicAdd(&g_cur[r1], 1) : 0;
    int p2 = (r2 >= 0) ? atomicAdd(&g_cur[r2], 1) : 0;
    int p3 = (r3 >= 0) ? atomicAdd(&g_cur[r3], 1) : 0;
    if (r0 >= 0) { g_ecol[p0] = ei[E + e0]; g_ewt[p0] = ew[e0]; }
    if (r1 >= 0) { g_ecol[p1] = ei[E + e1]; g_ewt[p1] = ew[e1]; }
    if (r2 >= 0) { g_ecol[p2] = ei[E + e2]; g_ewt[p2] = ew[e2]; }
    if (r3 >= 0) { g_ecol[p3] = ei[E + e3]; g_ewt[p3] = ew[e3]; }
}

// ---------------- k5: per-node gather aggregate + h*h (MLP-4) ----------------
__global__ void __launch_bounds__(256) k5_agg(float* __restrict__ out, int N) {
    int n = blockIdx.x * 8 + (threadIdx.x >> 5);
    if (n >= N) return;
    int lane = threadIdx.x & 31;
    int s = g_off[n];
    int e = s + g_deg[n];
    const float4* h4 = (const float4*)g_h;
    float4 acc = {0.f, 0.f, 0.f, 0.f};
    int j = s;
    for (; j + 4 <= e; j += 4) {
        int c0 = __ldg(&g_ecol[j]),     c1 = __ldg(&g_ecol[j + 1]);
        int c2 = __ldg(&g_ecol[j + 2]), c3 = __ldg(&g_ecol[j + 3]);
        float w0 = __ldg(&g_ewt[j]),     w1 = __ldg(&g_ewt[j + 1]);
        float w2 = __ldg(&g_ewt[j + 2]), w3 = __ldg(&g_ewt[j + 3]);
        float4 v0 = h4[(size_t)c0 * 32 + lane];
        float4 v1 = h4[(size_t)c1 * 32 + lane];
        float4 v2 = h4[(size_t)c2 * 32 + lane];
        float4 v3 = h4[(size_t)c3 * 32 + lane];
        acc.x = fmaf(w0, v0.x, acc.x); acc.y = fmaf(w0, v0.y, acc.y);
        acc.z = fmaf(w0, v0.z, acc.z); acc.w = fmaf(w0, v0.w, acc.w);
        acc.x = fmaf(w1, v1.x, acc.x); acc.y = fmaf(w1, v1.y, acc.y);
        acc.z = fmaf(w1, v1.z, acc.z); acc.w = fmaf(w1, v1.w, acc.w);
        acc.x = fmaf(w2, v2.x, acc.x); acc.y = fmaf(w2, v2.y, acc.y);
        acc.z = fmaf(w2, v2.z, acc.z); acc.w = fmaf(w2, v2.w, acc.w);
        acc.x = fmaf(w3, v3.x, acc.x); acc.y = fmaf(w3, v3.y, acc.y);
        acc.z = fmaf(w3, v3.z, acc.z); acc.w = fmaf(w3, v3.w, acc.w);
    }
    for (; j < e; j++) {
        int c0 = __ldg(&g_ecol[j]);
        float w0 = __ldg(&g_ewt[j]);
        float4 v0 = h4[(size_t)c0 * 32 + lane];
        acc.x = fmaf(w0, v0.x, acc.x); acc.y = fmaf(w0, v0.y, acc.y);
        acc.z = fmaf(w0, v0.z, acc.z); acc.w = fmaf(w0, v0.w, acc.w);
    }
    float4 hv = h4[(size_t)n * 32 + lane];
    float4 o;
    o.x = fmaf(hv.x, hv.x, acc.x);
    o.y = fmaf(hv.y, hv.y, acc.y);
    o.z = fmaf(hv.z, hv.z, acc.z);
    o.w = fmaf(hv.w, hv.w, acc.w);
    __stcs(&((float4*)out)[(size_t)n * 32 + lane], o);
}

// ---------------- launch: fork CSR chain onto a side stream ----------------
extern "C" void kernel_launch(void* const* d_in, const int* in_sizes, int n_in,
                              void* d_out, int out_size) {
    const float* n_feat = (const float*)d_in[0];
    const int*   ei     = (const int*)d_in[1];
    const float* ew     = (const float*)d_in[2];
    const float* gamma  = (const float*)d_in[3];
    const float* beta   = (const float*)d_in[4];
    const float* W      = (const float*)d_in[5];
    float* out = (float*)d_out;

    int N = in_sizes[0] / D;
    int E = in_sizes[2];
    int ntiles = (N + TILE_M - 1) / TILE_M;

    cudaStream_t s2;
    cudaStreamCreateWithFlags(&s2, cudaStreamNonBlocking);
    cudaEvent_t ev_fork, ev_join;
    cudaEventCreateWithFlags(&ev_fork, cudaEventDisableTiming);
    cudaEventCreateWithFlags(&ev_join, cudaEventDisableTiming);

    k0a_zero<<<NB256, 256>>>();
    cudaEventRecord(ev_fork, 0);

    cudaStreamWaitEvent(s2, ev_fork, 0);
    k4a_hist<<<(E + 1023) / 1024, 256, 0, s2>>>(ei, E);
    k4b_off<<<(N + 255) / 256, 256, 0, s2>>>(N);
    k4c_fill<<<(E + 1023) / 1024, 256, 0, s2>>>(ei, ew, E);
    cudaEventRecord(ev_join, s2);

    k0b_wprep<<<64, 256>>>(W);
    k1_stats<<<264, 256>>>((const float4*)n_feat, N);
    k2_final<<<1, D>>>(gamma, beta, 1.0f / (float)N);
    cudaFuncSetAttribute(k3_mma, cudaFuncAttributeMaxDynamicSharedMemorySize, SM_TOTAL);
    k3_mma<<<296, 256, SM_TOTAL>>>(n_feat, N, ntiles);

    cudaStreamWaitEvent(0, ev_join, 0);
    k5_agg<<<(N + 7) / 8, 256>>>(out, N);

    cudaEventDestroy(ev_fork);
    cudaEventDestroy(ev_join);
    cudaStreamDestroy(s2);
}

// round 10
// speedup vs baseline: 1.1335x; 1.0438x over previous
#include <cuda_runtime.h>
#include <cuda_fp16.h>
#include <cstdint>

#define D 128
#define MAXN 100000
#define MAXE 400000
#define TILE_M 64
#define NB256 391            // (MAXN+255)/256

// ---------------- scratch (allocation-free: device globals) ----------------
__device__ float g_stats[2 * D];                    // col sums / sumsq
__device__ float g_ab[2 * D];                       // BN affine a / b
__device__ unsigned short g_Whi[D * 136];           // fp16 hi, padded [n][k] stride 136
__device__ unsigned short g_Wlo[D * 136];           // fp16 lo
__device__ float g_h[(size_t)MAXN * D];             // h (51.2 MB)
__device__ int   g_deg[MAXN];
__device__ int   g_off[MAXN];
__device__ int   g_cur[MAXN];
__device__ int   g_total;
__device__ int   g_ecol[MAXE];
__device__ float g_ewt[MAXE];

// ---------------- helpers ----------------
__device__ __forceinline__ uint32_t smem_u32(const void* p) {
    uint32_t a;
    asm("{ .reg .u64 t; cvta.to.shared.u64 t, %1; cvt.u32.u64 %0, t; }" : "=r"(a) : "l"(p));
    return a;
}
__device__ __forceinline__ void ldmx4(uint32_t addr, uint32_t r[4]) {
    asm volatile("ldmatrix.sync.aligned.m8n8.x4.shared.b16 {%0,%1,%2,%3}, [%4];"
                 : "=r"(r[0]), "=r"(r[1]), "=r"(r[2]), "=r"(r[3]) : "r"(addr));
}
__device__ __forceinline__ void mma16816h(float c[4], const uint32_t a[4], const uint32_t b[2]) {
    asm volatile("mma.sync.aligned.m16n8k16.row.col.f32.f16.f16.f32 "
                 "{%0,%1,%2,%3}, {%4,%5,%6,%7}, {%8,%9}, {%0,%1,%2,%3};"
                 : "+f"(c[0]), "+f"(c[1]), "+f"(c[2]), "+f"(c[3])
                 : "r"(a[0]), "r"(a[1]), "r"(a[2]), "r"(a[3]), "r"(b[0]), "r"(b[1]));
}

// ---------------- k0a: zero CSR + stats scratch ----------------
__global__ void k0a_zero() {
    int i = blockIdx.x * 256 + threadIdx.x;
    if (i == 0) g_total = 0;
    if (i < 2 * D) g_stats[i] = 0.0f;
    if (i < MAXN) g_deg[i] = 0;
}
// ---------------- k0b: build padded W fp16 hi/lo ----------------
__global__ void k0b_wprep(const float* __restrict__ W) {
    int i = blockIdx.x * 256 + threadIdx.x;
    if (i < D * D) {
        int n = i >> 7, k = i & 127;
        float w = W[i];
        __half hi = __float2half_rn(w);
        float lf = w - __half2float(hi);
        g_Whi[n * 136 + k] = __half_as_ushort(hi);
        g_Wlo[n * 136 + k] = __half_as_ushort(__float2half_rn(lf));
    }
}

// ---------------- k1: column sums / sumsq ----------------
__global__ void __launch_bounds__(256) k1_stats(const float4* __restrict__ x4, int nrows) {
    int tx = threadIdx.x & 31, ty = threadIdx.x >> 5;
    float4 s = {0.f, 0.f, 0.f, 0.f}, q = {0.f, 0.f, 0.f, 0.f};
    for (int r = blockIdx.x * 8 + ty; r < nrows; r += gridDim.x * 8) {
        float4 v = x4[(size_t)r * 32 + tx];
        s.x += v.x; s.y += v.y; s.z += v.z; s.w += v.w;
        q.x += v.x * v.x; q.y += v.y * v.y; q.z += v.z * v.z; q.w += v.w * v.w;
    }
    __shared__ float4 rs[8][32], rq[8][32];
    rs[ty][tx] = s; rq[ty][tx] = q;
    __syncthreads();
    if (ty == 0) {
        for (int w = 1; w < 8; w++) {
            float4 a = rs[w][tx], b = rq[w][tx];
            s.x += a.x; s.y += a.y; s.z += a.z; s.w += a.w;
            q.x += b.x; q.y += b.y; q.z += b.z; q.w += b.w;
        }
        atomicAdd(&g_stats[4 * tx + 0], s.x);
        atomicAdd(&g_stats[4 * tx + 1], s.y);
        atomicAdd(&g_stats[4 * tx + 2], s.z);
        atomicAdd(&g_stats[4 * tx + 3], s.w);
        atomicAdd(&g_stats[D + 4 * tx + 0], q.x);
        atomicAdd(&g_stats[D + 4 * tx + 1], q.y);
        atomicAdd(&g_stats[D + 4 * tx + 2], q.z);
        atomicAdd(&g_stats[D + 4 * tx + 3], q.w);
    }
}

// ---------------- k2: finalize BN affine ----------------
__global__ void k2_final(const float* __restrict__ gamma, const float* __restrict__ beta, float inv_n) {
    int c = threadIdx.x;
    float mu  = g_stats[c] * inv_n;
    float var = fmaxf(g_stats[D + c] * inv_n - mu * mu, 0.0f);
    float a = gamma[c] * rsqrtf(var + 1e-5f);
    g_ab[c] = a;
    g_ab[D + c] = beta[c] - mu * a;
}

// ---------------- k3: HMMA fp16 W-split GEMM (2 products) + prefetch ----------------
// smem: Whi(34816) | Wlo(34816) | Xhi(17408) = 87040 B per CTA, 2 CTAs/SM
#define SM_WHI 0
#define SM_WLO 34816
#define SM_XHI 69632
#define SM_TOTAL 87040
#define XSTR 272     // row stride bytes

__global__ void __launch_bounds__(256, 2) k3_mma(const float* __restrict__ x,
                                                 int nrows, int ntiles) {
    extern __shared__ __align__(16) char sm[];
    uint32_t smb = smem_u32(sm);
    int tid = threadIdx.x, wid = tid >> 5, lane = tid & 31;
    int warp_m = wid & 1;       // 2 m-blocks of 32 rows
    int warp_n = wid >> 1;      // 4 n-blocks of 32 cols

    {
        const uint4* hs = (const uint4*)g_Whi;
        const uint4* ls = (const uint4*)g_Wlo;
        uint4* hd = (uint4*)(sm + SM_WHI);
        uint4* ld = (uint4*)(sm + SM_WLO);
        for (int i = tid; i < 2176; i += 256) { hd[i] = hs[i]; ld[i] = ls[i]; }
    }

    int laneRowA = (lane & 7) + ((lane >> 3) & 1) * 8;
    int laneKA   = (lane >> 4) * 8;
    int laneRowB = (lane & 7) + ((lane >> 4) & 1) * 8;
    int laneKB   = ((lane >> 3) & 1) * 8;
    uint32_t aoff = (uint32_t)((warp_m * 32 + laneRowA) * XSTR + laneKA * 2);
    uint32_t boff = (uint32_t)((warp_n * 32 + laneRowB) * XSTR + laneKB * 2);
    uint32_t a_hi = smb + SM_XHI + aoff;
    uint32_t b_hi = smb + SM_WHI + boff, b_lo = smb + SM_WLO + boff;

    const float4* x4 = (const float4*)x;
    int row_in = tid >> 5;
    int cq = tid & 31;
    float4 aba = ((const float4*)g_ab)[cq];
    float4 abb = ((const float4*)g_ab)[32 + cq];

    // prefetch first tile into regs
    float4 v[8];
    {
        int t0 = blockIdx.x;
        #pragma unroll
        for (int it = 0; it < 8; it++) {
            int gr = t0 * TILE_M + row_in + it * 8;
            v[it] = (t0 < ntiles && gr < nrows) ? x4[(size_t)gr * 32 + cq]
                                                : make_float4(0.f, 0.f, 0.f, 0.f);
        }
    }

    for (int t = blockIdx.x; t < ntiles; t += gridDim.x) {
        // ---- convert regs -> fp16 -> STS ----
        #pragma unroll
        for (int it = 0; it < 8; it++) {
            int r = row_in + it * 8;
            float y0 = fmaxf(fmaf(aba.x, v[it].x, abb.x), 0.f);
            float y1 = fmaxf(fmaf(aba.y, v[it].y, abb.y), 0.f);
            float y2 = fmaxf(fmaf(aba.z, v[it].z, abb.z), 0.f);
            float y3 = fmaxf(fmaf(aba.w, v[it].w, abb.w), 0.f);
            __half2 p01 = __floats2half2_rn(y0, y1);
            __half2 p23 = __floats2half2_rn(y2, y3);
            uint2 hiw;
            hiw.x = *(uint32_t*)&p01;
            hiw.y = *(uint32_t*)&p23;
            uint32_t off = (uint32_t)(r * XSTR + cq * 8);
            *(uint2*)(sm + SM_XHI + off) = hiw;
        }
        __syncthreads();

        // ---- issue prefetch of next tile (hides under MMAs) ----
        {
            int tn = t + gridDim.x;
            #pragma unroll
            for (int it = 0; it < 8; it++) {
                int gr = tn * TILE_M + row_in + it * 8;
                if (tn < ntiles && gr < nrows) v[it] = x4[(size_t)gr * 32 + cq];
                else v[it] = make_float4(0.f, 0.f, 0.f, 0.f);
            }
        }

        // ---- mainloop: 8 k16-steps x 2 products ----
        float acc[2][4][4];
        #pragma unroll
        for (int mt = 0; mt < 2; mt++)
            #pragma unroll
            for (int nt = 0; nt < 4; nt++)
                #pragma unroll
                for (int j = 0; j < 4; j++) acc[mt][nt][j] = 0.f;

        for (int ko = 0; ko < 8; ko++) {
            uint32_t kb = ko * 32;
            uint32_t ah[2][4];
            #pragma unroll
            for (int mt = 0; mt < 2; mt++)
                ldmx4(a_hi + mt * (16 * XSTR) + kb, ah[mt]);
            uint32_t bh[4][2], bl[4][2];
            #pragma unroll
            for (int np = 0; np < 2; np++) {
                uint32_t tm[4];
                ldmx4(b_hi + np * (16 * XSTR) + kb, tm);
                bh[2*np][0] = tm[0]; bh[2*np][1] = tm[1];
                bh[2*np+1][0] = tm[2]; bh[2*np+1][1] = tm[3];
                ldmx4(b_lo + np * (16 * XSTR) + kb, tm);
                bl[2*np][0] = tm[0]; bl[2*np][1] = tm[1];
                bl[2*np+1][0] = tm[2]; bl[2*np+1][1] = tm[3];
            }
            #pragma unroll
            for (int mt = 0; mt < 2; mt++)
                #pragma unroll
                for (int nt = 0; nt < 4; nt++) {
                    mma16816h(acc[mt][nt], ah[mt], bh[nt]);
                    mma16816h(acc[mt][nt], ah[mt], bl[nt]);
                }
        }

        // ---- epilogue: write h ----
        int rbase = t * TILE_M + warp_m * 32 + (lane >> 2);
        int cbase = warp_n * 32 + 2 * (lane & 3);
        #pragma unroll
        for (int mt = 0; mt < 2; mt++) {
            #pragma unroll
            for (int nt = 0; nt < 4; nt++) {
                int r0 = rbase + mt * 16;
                int c = cbase + nt * 8;
                if (r0 < nrows)
                    *(float2*)&g_h[(size_t)r0 * D + c] = make_float2(acc[mt][nt][0], acc[mt][nt][1]);
                if (r0 + 8 < nrows)
                    *(float2*)&g_h[(size_t)(r0 + 8) * D + c] = make_float2(acc[mt][nt][2], acc[mt][nt][3]);
            }
        }
        __syncthreads();
    }
}

// ---------------- CSR build ----------------
__global__ void __launch_bounds__(256) k4a_hist(const int* __restrict__ ei, int E) {
    int base = blockIdx.x * 1024 + threadIdx.x;
    #pragma unroll
    for (int j = 0; j < 4; j++) {
        int e = base + j * 256;
        if (e < E) atomicAdd(&g_deg[ei[e]], 1);
    }
}
__global__ void __launch_bounds__(256) k4b_off(int N) {
    int i = blockIdx.x * 256 + threadIdx.x;
    int lane = threadIdx.x & 31;
    int v = (i < N) ? g_deg[i] : 0;
    int incl = v;
    #pragma unroll
    for (int o = 1; o < 32; o <<= 1) {
        int t = __shfl_up_sync(0xFFFFFFFFu, incl, o);
        if (lane >= o) incl += t;
    }
    int wsum = __shfl_sync(0xFFFFFFFFu, incl, 31);
    int base = 0;
    if (lane == 0) base = atomicAdd(&g_total, wsum);
    base = __shfl_sync(0xFFFFFFFFu, base, 0);
    if (i < N) {
        int off = base + incl - v;
        g_off[i] = off;
        g_cur[i] = off;
    }
}
__global__ void __launch_bounds__(256) k4c_fill(const int* __restrict__ ei,
                                                const float* __restrict__ ew, int E) {
    int base = blockIdx.x * 1024 + threadIdx.x;
    int e0 = base, e1 = base + 256, e2 = base + 512, e3 = base + 768;
    int r0 = (e0 < E) ? ei[e0] : -1;
    int r1 = (e1 < E) ? ei[e1] : -1;
    int r2 = (e2 < E) ? ei[e2] : -1;
    int r3 = (e3 < E) ? ei[e3] : -1;
    int p0 = (r0 >= 0) ? atomicAdd(&g_cur[r0], 1) : 0;
    int p1 = (r1 >= 0) ? atomicAdd(&g_cur[r1], 1) : 0;
    int p2 = (r2 >= 0) ? atomicAdd(&g_cur[r2], 1) : 0;
    int p3 = (r3 >= 0) ? atomicAdd(&g_cur[r3], 1) : 0;
    if (r0 >= 0) { g_ecol[p0] = ei[E + e0]; g_ewt[p0] = ew[e0]; }
    if (r1 >= 0) { g_ecol[p1] = ei[E + e1]; g_ewt[p1] = ew[e1]; }
    if (r2 >= 0) { g_ecol[p2] = ei[E + e2]; g_ewt[p2] = ew[e2]; }
    if (r3 >= 0) { g_ecol[p3] = ei[E + e3]; g_ewt[p3] = ew[e3]; }
}

// ---------------- k5: per-node gather aggregate + h*h (MLP-4) ----------------
__global__ void __launch_bounds__(256) k5_agg(float* __restrict__ out, int N) {
    int n = blockIdx.x * 8 + (threadIdx.x >> 5);
    if (n >= N) return;
    int lane = threadIdx.x & 31;
    int s = g_off[n];
    int e = s + g_deg[n];
    const float4* h4 = (const float4*)g_h;
    float4 acc = {0.f, 0.f, 0.f, 0.f};
    int j = s;
    for (; j + 4 <= e; j += 4) {
        int c0 = __ldg(&g_ecol[j]),     c1 = __ldg(&g_ecol[j + 1]);
        int c2 = __ldg(&g_ecol[j + 2]), c3 = __ldg(&g_ecol[j + 3]);
        float w0 = __ldg(&g_ewt[j]),     w1 = __ldg(&g_ewt[j + 1]);
        float w2 = __ldg(&g_ewt[j + 2]), w3 = __ldg(&g_ewt[j + 3]);
        float4 v0 = h4[(size_t)c0 * 32 + lane];
        float4 v1 = h4[(size_t)c1 * 32 + lane];
        float4 v2 = h4[(size_t)c2 * 32 + lane];
        float4 v3 = h4[(size_t)c3 * 32 + lane];
        acc.x = fmaf(w0, v0.x, acc.x); acc.y = fmaf(w0, v0.y, acc.y);
        acc.z = fmaf(w0, v0.z, acc.z); acc.w = fmaf(w0, v0.w, acc.w);
        acc.x = fmaf(w1, v1.x, acc.x); acc.y = fmaf(w1, v1.y, acc.y);
        acc.z = fmaf(w1, v1.z, acc.z); acc.w = fmaf(w1, v1.w, acc.w);
        acc.x = fmaf(w2, v2.x, acc.x); acc.y = fmaf(w2, v2.y, acc.y);
        acc.z = fmaf(w2, v2.z, acc.z); acc.w = fmaf(w2, v2.w, acc.w);
        acc.x = fmaf(w3, v3.x, acc.x); acc.y = fmaf(w3, v3.y, acc.y);
        acc.z = fmaf(w3, v3.z, acc.z); acc.w = fmaf(w3, v3.w, acc.w);
    }
    for (; j < e; j++) {
        int c0 = __ldg(&g_ecol[j]);
        float w0 = __ldg(&g_ewt[j]);
        float4 v0 = h4[(size_t)c0 * 32 + lane];
        acc.x = fmaf(w0, v0.x, acc.x); acc.y = fmaf(w0, v0.y, acc.y);
        acc.z = fmaf(w0, v0.z, acc.z); acc.w = fmaf(w0, v0.w, acc.w);
    }
    float4 hv = h4[(size_t)n * 32 + lane];
    float4 o;
    o.x = fmaf(hv.x, hv.x, acc.x);
    o.y = fmaf(hv.y, hv.y, acc.y);
    o.z = fmaf(hv.z, hv.z, acc.z);
    o.w = fmaf(hv.w, hv.w, acc.w);
    __stcs(&((float4*)out)[(size_t)n * 32 + lane], o);
}

// ---------------- launch: fork CSR chain onto a side stream ----------------
extern "C" void kernel_launch(void* const* d_in, const int* in_sizes, int n_in,
                              void* d_out, int out_size) {
    const float* n_feat = (const float*)d_in[0];
    const int*   ei     = (const int*)d_in[1];
    const float* ew     = (const float*)d_in[2];
    const float* gamma  = (const float*)d_in[3];
    const float* beta   = (const float*)d_in[4];
    const float* W      = (const float*)d_in[5];
    float* out = (float*)d_out;

    int N = in_sizes[0] / D;
    int E = in_sizes[2];
    int ntiles = (N + TILE_M - 1) / TILE_M;

    cudaStream_t s2;
    cudaStreamCreateWithFlags(&s2, cudaStreamNonBlocking);
    cudaEvent_t ev_fork, ev_join;
    cudaEventCreateWithFlags(&ev_fork, cudaEventDisableTiming);
    cudaEventCreateWithFlags(&ev_join, cudaEventDisableTiming);

    k0a_zero<<<NB256, 256>>>();
    cudaEventRecord(ev_fork, 0);

    cudaStreamWaitEvent(s2, ev_fork, 0);
    k4a_hist<<<(E + 1023) / 1024, 256, 0, s2>>>(ei, E);
    k4b_off<<<(N + 255) / 256, 256, 0, s2>>>(N);
    k4c_fill<<<(E + 1023) / 1024, 256, 0, s2>>>(ei, ew, E);
    cudaEventRecord(ev_join, s2);

    k0b_wprep<<<64, 256>>>(W);
    k1_stats<<<264, 256>>>((const float4*)n_feat, N);
    k2_final<<<1, D>>>(gamma, beta, 1.0f / (float)N);
    cudaFuncSetAttribute(k3_mma, cudaFuncAttributeMaxDynamicSharedMemorySize, SM_TOTAL);
    k3_mma<<<296, 256, SM_TOTAL>>>(n_feat, N, ntiles);

    cudaStreamWaitEvent(0, ev_join, 0);
    k5_agg<<<(N + 7) / 8, 256>>>(out, N);

    cudaEventDestroy(ev_fork);
    cudaEventDestroy(ev_join);
    cudaStreamDestroy(s2);
}

// round 11
// speedup vs baseline: 1.2242x; 1.0800x over previous
#include <cuda_runtime.h>
#include <cuda_fp16.h>
#include <cstdint>

#define D 128
#define MAXN 100000
#define MAXE 400000
#define TILE_M 64
#define NB256 391            // (MAXN+255)/256

// ---------------- scratch (allocation-free: device globals) ----------------
__device__ float g_stats[2 * D];                    // col sums / sumsq
__device__ float g_ab[2 * D];                       // BN affine a / b
__device__ unsigned short g_Whi[D * 136];           // fp16 W, padded [n][k] stride 136
__device__ float g_h[(size_t)MAXN * D];             // h (51.2 MB)
__device__ int   g_deg[MAXN];
__device__ int   g_off[MAXN];
__device__ int   g_cur[MAXN];
__device__ int   g_total;
__device__ int   g_k1done;
__device__ int   g_ecol[MAXE];
__device__ float g_ewt[MAXE];

// ---------------- helpers ----------------
__device__ __forceinline__ uint32_t smem_u32(const void* p) {
    uint32_t a;
    asm("{ .reg .u64 t; cvta.to.shared.u64 t, %1; cvt.u32.u64 %0, t; }" : "=r"(a) : "l"(p));
    return a;
}
__device__ __forceinline__ void ldmx4(uint32_t addr, uint32_t r[4]) {
    asm volatile("ldmatrix.sync.aligned.m8n8.x4.shared.b16 {%0,%1,%2,%3}, [%4];"
                 : "=r"(r[0]), "=r"(r[1]), "=r"(r[2]), "=r"(r[3]) : "r"(addr));
}
__device__ __forceinline__ void mma16816h(float c[4], const uint32_t a[4], const uint32_t b[2]) {
    asm volatile("mma.sync.aligned.m16n8k16.row.col.f32.f16.f16.f32 "
                 "{%0,%1,%2,%3}, {%4,%5,%6,%7}, {%8,%9}, {%0,%1,%2,%3};"
                 : "+f"(c[0]), "+f"(c[1]), "+f"(c[2]), "+f"(c[3])
                 : "r"(a[0]), "r"(a[1]), "r"(a[2]), "r"(a[3]), "r"(b[0]), "r"(b[1]));
}

// ---------------- k0: zero scratch + build padded fp16 W ----------------
__global__ void k0_prep(const float* __restrict__ W) {
    int i = blockIdx.x * 256 + threadIdx.x;
    if (i == 0) { g_total = 0; g_k1done = 0; }
    if (i < 2 * D) g_stats[i] = 0.0f;
    if (i < MAXN) g_deg[i] = 0;
    if (i < D * D) {
        int n = i >> 7, k = i & 127;
        g_Whi[n * 136 + k] = __half_as_ushort(__float2half_rn(W[i]));
    }
}

// ---------------- k1: column sums / sumsq + fused affine finalize ----------------
__global__ void __launch_bounds__(256) k1_stats(const float4* __restrict__ x4,
                                                const float* __restrict__ gamma,
                                                const float* __restrict__ beta,
                                                int nrows, float inv_n) {
    int tx = threadIdx.x & 31, ty = threadIdx.x >> 5;
    float4 s = {0.f, 0.f, 0.f, 0.f}, q = {0.f, 0.f, 0.f, 0.f};
    for (int r = blockIdx.x * 8 + ty; r < nrows; r += gridDim.x * 8) {
        float4 v = x4[(size_t)r * 32 + tx];
        s.x += v.x; s.y += v.y; s.z += v.z; s.w += v.w;
        q.x += v.x * v.x; q.y += v.y * v.y; q.z += v.z * v.z; q.w += v.w * v.w;
    }
    __shared__ float4 rs[8][32], rq[8][32];
    __shared__ int slast;
    rs[ty][tx] = s; rq[ty][tx] = q;
    __syncthreads();
    if (ty == 0) {
        for (int w = 1; w < 8; w++) {
            float4 a = rs[w][tx], b = rq[w][tx];
            s.x += a.x; s.y += a.y; s.z += a.z; s.w += a.w;
            q.x += b.x; q.y += b.y; q.z += b.z; q.w += b.w;
        }
        atomicAdd(&g_stats[4 * tx + 0], s.x);
        atomicAdd(&g_stats[4 * tx + 1], s.y);
        atomicAdd(&g_stats[4 * tx + 2], s.z);
        atomicAdd(&g_stats[4 * tx + 3], s.w);
        atomicAdd(&g_stats[D + 4 * tx + 0], q.x);
        atomicAdd(&g_stats[D + 4 * tx + 1], q.y);
        atomicAdd(&g_stats[D + 4 * tx + 2], q.z);
        atomicAdd(&g_stats[D + 4 * tx + 3], q.w);
        __threadfence();
    }
    __syncthreads();
    if (threadIdx.x == 0) {
        int t = atomicAdd(&g_k1done, 1);
        slast = (t == gridDim.x - 1) ? 1 : 0;
    }
    __syncthreads();
    if (slast && threadIdx.x < D) {
        int c = threadIdx.x;
        float ssum = __ldcg(&g_stats[c]);
        float qsum = __ldcg(&g_stats[D + c]);
        float mu  = ssum * inv_n;
        float var = fmaxf(qsum * inv_n - mu * mu, 0.0f);
        float a = gamma[c] * rsqrtf(var + 1e-5f);
        g_ab[c] = a;
        g_ab[D + c] = beta[c] - mu * a;
    }
}

// ---------------- k3: HMMA fp16 single-product GEMM + prefetch ----------------
// smem: Whi(34816) | Xhi(17408) = 52224 B per CTA, 2 CTAs/SM
#define SM_WHI 0
#define SM_XHI 34816
#define SM_TOTAL 52224
#define XSTR 272     // row stride bytes

__global__ void __launch_bounds__(256, 2) k3_mma(const float* __restrict__ x,
                                                 int nrows, int ntiles) {
    extern __shared__ __align__(16) char sm[];
    uint32_t smb = smem_u32(sm);
    int tid = threadIdx.x, wid = tid >> 5, lane = tid & 31;
    int warp_m = wid & 1;       // 2 m-blocks of 32 rows
    int warp_n = wid >> 1;      // 4 n-blocks of 32 cols

    {
        const uint4* hs = (const uint4*)g_Whi;
        uint4* hd = (uint4*)(sm + SM_WHI);
        for (int i = tid; i < 2176; i += 256) hd[i] = hs[i];
    }

    int laneRowA = (lane & 7) + ((lane >> 3) & 1) * 8;
    int laneKA   = (lane >> 4) * 8;
    int laneRowB = (lane & 7) + ((lane >> 4) & 1) * 8;
    int laneKB   = ((lane >> 3) & 1) * 8;
    uint32_t aoff = (uint32_t)((warp_m * 32 + laneRowA) * XSTR + laneKA * 2);
    uint32_t boff = (uint32_t)((warp_n * 32 + laneRowB) * XSTR + laneKB * 2);
    uint32_t a_hi = smb + SM_XHI + aoff;
    uint32_t b_hi = smb + SM_WHI + boff;

    const float4* x4 = (const float4*)x;
    int row_in = tid >> 5;
    int cq = tid & 31;
    float4 aba = ((const float4*)g_ab)[cq];
    float4 abb = ((const float4*)g_ab)[32 + cq];

    // prefetch first tile into regs
    float4 v[8];
    {
        int t0 = blockIdx.x;
        #pragma unroll
        for (int it = 0; it < 8; it++) {
            int gr = t0 * TILE_M + row_in + it * 8;
            v[it] = (t0 < ntiles && gr < nrows) ? x4[(size_t)gr * 32 + cq]
                                                : make_float4(0.f, 0.f, 0.f, 0.f);
        }
    }

    for (int t = blockIdx.x; t < ntiles; t += gridDim.x) {
        // ---- convert regs -> fp16 -> STS ----
        #pragma unroll
        for (int it = 0; it < 8; it++) {
            int r = row_in + it * 8;
            float y0 = fmaxf(fmaf(aba.x, v[it].x, abb.x), 0.f);
            float y1 = fmaxf(fmaf(aba.y, v[it].y, abb.y), 0.f);
            float y2 = fmaxf(fmaf(aba.z, v[it].z, abb.z), 0.f);
            float y3 = fmaxf(fmaf(aba.w, v[it].w, abb.w), 0.f);
            __half2 p01 = __floats2half2_rn(y0, y1);
            __half2 p23 = __floats2half2_rn(y2, y3);
            uint2 hiw;
            hiw.x = *(uint32_t*)&p01;
            hiw.y = *(uint32_t*)&p23;
            uint32_t off = (uint32_t)(r * XSTR + cq * 8);
            *(uint2*)(sm + SM_XHI + off) = hiw;
        }
        __syncthreads();

        // ---- issue prefetch of next tile (hides under MMAs) ----
        {
            int tn = t + gridDim.x;
            #pragma unroll
            for (int it = 0; it < 8; it++) {
                int gr = tn * TILE_M + row_in + it * 8;
                if (tn < ntiles && gr < nrows) v[it] = x4[(size_t)gr * 32 + cq];
                else v[it] = make_float4(0.f, 0.f, 0.f, 0.f);
            }
        }

        // ---- mainloop: 8 k16-steps x 1 product ----
        float acc[2][4][4];
        #pragma unroll
        for (int mt = 0; mt < 2; mt++)
            #pragma unroll
            for (int nt = 0; nt < 4; nt++)
                #pragma unroll
                for (int j = 0; j < 4; j++) acc[mt][nt][j] = 0.f;

        for (int ko = 0; ko < 8; ko++) {
            uint32_t kb = ko * 32;
            uint32_t ah[2][4];
            #pragma unroll
            for (int mt = 0; mt < 2; mt++)
                ldmx4(a_hi + mt * (16 * XSTR) + kb, ah[mt]);
            uint32_t bh[4][2];
            #pragma unroll
            for (int np = 0; np < 2; np++) {
                uint32_t tm[4];
                ldmx4(b_hi + np * (16 * XSTR) + kb, tm);
                bh[2*np][0] = tm[0]; bh[2*np][1] = tm[1];
                bh[2*np+1][0] = tm[2]; bh[2*np+1][1] = tm[3];
            }
            #pragma unroll
            for (int mt = 0; mt < 2; mt++)
                #pragma unroll
                for (int nt = 0; nt < 4; nt++)
                    mma16816h(acc[mt][nt], ah[mt], bh[nt]);
        }

        // ---- epilogue: write h ----
        int rbase = t * TILE_M + warp_m * 32 + (lane >> 2);
        int cbase = warp_n * 32 + 2 * (lane & 3);
        #pragma unroll
        for (int mt = 0; mt < 2; mt++) {
            #pragma unroll
            for (int nt = 0; nt < 4; nt++) {
                int r0 = rbase + mt * 16;
                int c = cbase + nt * 8;
                if (r0 < nrows)
                    *(float2*)&g_h[(size_t)r0 * D + c] = make_float2(acc[mt][nt][0], acc[mt][nt][1]);
                if (r0 + 8 < nrows)
                    *(float2*)&g_h[(size_t)(r0 + 8) * D + c] = make_float2(acc[mt][nt][2], acc[mt][nt][3]);
            }
        }
        __syncthreads();
    }
}

// ---------------- CSR build ----------------
__global__ void __launch_bounds__(256) k4a_hist(const int* __restrict__ ei, int E) {
    int base = blockIdx.x * 1024 + threadIdx.x;
    #pragma unroll
    for (int j = 0; j < 4; j++) {
        int e = base + j * 256;
        if (e < E) atomicAdd(&g_deg[ei[e]], 1);
    }
}
__global__ void __launch_bounds__(256) k4b_off(int N) {
    int i = blockIdx.x * 256 + threadIdx.x;
    int lane = threadIdx.x & 31;
    int v = (i < N) ? g_deg[i] : 0;
    int incl = v;
    #pragma unroll
    for (int o = 1; o < 32; o <<= 1) {
        int t = __shfl_up_sync(0xFFFFFFFFu, incl, o);
        if (lane >= o) incl += t;
    }
    int wsum = __shfl_sync(0xFFFFFFFFu, incl, 31);
    int base = 0;
    if (lane == 0) base = atomicAdd(&g_total, wsum);
    base = __shfl_sync(0xFFFFFFFFu, base, 0);
    if (i < N) {
        int off = base + incl - v;
        g_off[i] = off;
        g_cur[i] = off;
    }
}
__global__ void __launch_bounds__(256) k4c_fill(const int* __restrict__ ei,
                                                const float* __restrict__ ew, int E) {
    int base = blockIdx.x * 1024 + threadIdx.x;
    int e0 = base, e1 = base + 256, e2 = base + 512, e3 = base + 768;
    int r0 = (e0 < E) ? ei[e0] : -1;
    int r1 = (e1 < E) ? ei[e1] : -1;
    int r2 = (e2 < E) ? ei[e2] : -1;
    int r3 = (e3 < E) ? ei[e3] : -1;
    int p0 = (r0 >= 0) ? atomicAdd(&g_cur[r0], 1) : 0;
    int p1 = (r1 >= 0) ? atomicAdd(&g_cur[r1], 1) : 0;
    int p2 = (r2 >= 0) ? atomicAdd(&g_cur[r2], 1) : 0;
    int p3 = (r3 >= 0) ? atomicAdd(&g_cur[r3], 1) : 0;
    if (r0 >= 0) { g_ecol[p0] = ei[E + e0]; g_ewt[p0] = ew[e0]; }
    if (r1 >= 0) { g_ecol[p1] = ei[E + e1]; g_ewt[p1] = ew[e1]; }
    if (r2 >= 0) { g_ecol[p2] = ei[E + e2]; g_ewt[p2] = ew[e2]; }
    if (r3 >= 0) { g_ecol[p3] = ei[E + e3]; g_ewt[p3] = ew[e3]; }
}

// ---------------- k5: per-node gather aggregate + h*h (MLP-4) ----------------
__global__ void __launch_bounds__(256) k5_agg(float* __restrict__ out, int N) {
    int n = blockIdx.x * 8 + (threadIdx.x >> 5);
    if (n >= N) return;
    int lane = threadIdx.x & 31;
    int s = g_off[n];
    int e = s + g_deg[n];
    const float4* h4 = (const float4*)g_h;
    float4 acc = {0.f, 0.f, 0.f, 0.f};
    int j = s;
    for (; j + 4 <= e; j += 4) {
        int c0 = __ldg(&g_ecol[j]),     c1 = __ldg(&g_ecol[j + 1]);
        int c2 = __ldg(&g_ecol[j + 2]), c3 = __ldg(&g_ecol[j + 3]);
        float w0 = __ldg(&g_ewt[j]),     w1 = __ldg(&g_ewt[j + 1]);
        float w2 = __ldg(&g_ewt[j + 2]), w3 = __ldg(&g_ewt[j + 3]);
        float4 v0 = h4[(size_t)c0 * 32 + lane];
        float4 v1 = h4[(size_t)c1 * 32 + lane];
        float4 v2 = h4[(size_t)c2 * 32 + lane];
        float4 v3 = h4[(size_t)c3 * 32 + lane];
        acc.x = fmaf(w0, v0.x, acc.x); acc.y = fmaf(w0, v0.y, acc.y);
        acc.z = fmaf(w0, v0.z, acc.z); acc.w = fmaf(w0, v0.w, acc.w);
        acc.x = fmaf(w1, v1.x, acc.x); acc.y = fmaf(w1, v1.y, acc.y);
        acc.z = fmaf(w1, v1.z, acc.z); acc.w = fmaf(w1, v1.w, acc.w);
        acc.x = fmaf(w2, v2.x, acc.x); acc.y = fmaf(w2, v2.y, acc.y);
        acc.z = fmaf(w2, v2.z, acc.z); acc.w = fmaf(w2, v2.w, acc.w);
        acc.x = fmaf(w3, v3.x, acc.x); acc.y = fmaf(w3, v3.y, acc.y);
        acc.z = fmaf(w3, v3.z, acc.z); acc.w = fmaf(w3, v3.w, acc.w);
    }
    for (; j < e; j++) {
        int c0 = __ldg(&g_ecol[j]);
        float w0 = __ldg(&g_ewt[j]);
        float4 v0 = h4[(size_t)c0 * 32 + lane];
        acc.x = fmaf(w0, v0.x, acc.x); acc.y = fmaf(w0, v0.y, acc.y);
        acc.z = fmaf(w0, v0.z, acc.z); acc.w = fmaf(w0, v0.w, acc.w);
    }
    float4 hv = h4[(size_t)n * 32 + lane];
    float4 o;
    o.x = fmaf(hv.x, hv.x, acc.x);
    o.y = fmaf(hv.y, hv.y, acc.y);
    o.z = fmaf(hv.z, hv.z, acc.z);
    o.w = fmaf(hv.w, hv.w, acc.w);
    __stcs(&((float4*)out)[(size_t)n * 32 + lane], o);
}

// ---------------- launch: fork CSR chain onto a side stream ----------------
extern "C" void kernel_launch(void* const* d_in, const int* in_sizes, int n_in,
                              void* d_out, int out_size) {
    const float* n_feat = (const float*)d_in[0];
    const int*   ei     = (const int*)d_in[1];
    const float* ew     = (const float*)d_in[2];
    const float* gamma  = (const float*)d_in[3];
    const float* beta   = (const float*)d_in[4];
    const float* W      = (const float*)d_in[5];
    float* out = (float*)d_out;

    int N = in_sizes[0] / D;
    int E = in_sizes[2];
    int ntiles = (N + TILE_M - 1) / TILE_M;

    cudaStream_t s2;
    cudaStreamCreateWithFlags(&s2, cudaStreamNonBlocking);
    cudaEvent_t ev_fork, ev_join;
    cudaEventCreateWithFlags(&ev_fork, cudaEventDisableTiming);
    cudaEventCreateWithFlags(&ev_join, cudaEventDisableTiming);

    k0_prep<<<NB256, 256>>>(W);
    cudaEventRecord(ev_fork, 0);

    cudaStreamWaitEvent(s2, ev_fork, 0);
    k4a_hist<<<(E + 1023) / 1024, 256, 0, s2>>>(ei, E);
    k4b_off<<<(N + 255) / 256, 256, 0, s2>>>(N);
    k4c_fill<<<(E + 1023) / 1024, 256, 0, s2>>>(ei, ew, E);
    cudaEventRecord(ev_join, s2);

    k1_stats<<<264, 256>>>((const float4*)n_feat, gamma, beta, N, 1.0f / (float)N);
    cudaFuncSetAttribute(k3_mma, cudaFuncAttributeMaxDynamicSharedMemorySize, SM_TOTAL);
    k3_mma<<<296, 256, SM_TOTAL>>>(n_feat, N, ntiles);

    cudaStreamWaitEvent(0, ev_join, 0);
    k5_agg<<<(N + 7) / 8, 256>>>(out, N);

    cudaEventDestroy(ev_fork);
    cudaEventDestroy(ev_join);
    cudaStreamDestroy(s2);
}

// round 12
// speedup vs baseline: 1.2546x; 1.0249x over previous
#include <cuda_runtime.h>
#include <cuda_fp16.h>
#include <cstdint>

#define D 128
#define MAXN 100000
#define MAXE 400000
#define TILE_M 64
#define NB256 391            // (MAXN+255)/256

// ---------------- scratch (allocation-free: device globals) ----------------
__device__ float g_stats[2 * D];                    // col sums / sumsq
__device__ float g_ab[2 * D];                       // BN affine a / b
__device__ unsigned short g_Whi[D * 136];           // fp16 W, padded [n][k] stride 136
__device__ __half g_h[(size_t)MAXN * D];            // h fp16 (25.6 MB) — single copy
__device__ int   g_deg[MAXN];
__device__ int   g_off[MAXN];
__device__ int   g_cur[MAXN];
__device__ int   g_total;
__device__ int   g_k1done;
__device__ int   g_ecol[MAXE];
__device__ float g_ewt[MAXE];

// ---------------- helpers ----------------
__device__ __forceinline__ uint32_t smem_u32(const void* p) {
    uint32_t a;
    asm("{ .reg .u64 t; cvta.to.shared.u64 t, %1; cvt.u32.u64 %0, t; }" : "=r"(a) : "l"(p));
    return a;
}
__device__ __forceinline__ void ldmx4(uint32_t addr, uint32_t r[4]) {
    asm volatile("ldmatrix.sync.aligned.m8n8.x4.shared.b16 {%0,%1,%2,%3}, [%4];"
                 : "=r"(r[0]), "=r"(r[1]), "=r"(r[2]), "=r"(r[3]) : "r"(addr));
}
__device__ __forceinline__ void mma16816h(float c[4], const uint32_t a[4], const uint32_t b[2]) {
    asm volatile("mma.sync.aligned.m16n8k16.row.col.f32.f16.f16.f32 "
                 "{%0,%1,%2,%3}, {%4,%5,%6,%7}, {%8,%9}, {%0,%1,%2,%3};"
                 : "+f"(c[0]), "+f"(c[1]), "+f"(c[2]), "+f"(c[3])
                 : "r"(a[0]), "r"(a[1]), "r"(a[2]), "r"(a[3]), "r"(b[0]), "r"(b[1]));
}

// ---------------- k0: zero scratch + build padded fp16 W ----------------
__global__ void k0_prep(const float* __restrict__ W) {
    int i = blockIdx.x * 256 + threadIdx.x;
    if (i == 0) { g_total = 0; g_k1done = 0; }
    if (i < 2 * D) g_stats[i] = 0.0f;
    if (i < MAXN) g_deg[i] = 0;
    if (i < D * D) {
        int n = i >> 7, k = i & 127;
        g_Whi[n * 136 + k] = __half_as_ushort(__float2half_rn(W[i]));
    }
}

// ---------------- k1: column sums / sumsq + fused affine finalize ----------------
__global__ void __launch_bounds__(256) k1_stats(const float4* __restrict__ x4,
                                                const float* __restrict__ gamma,
                                                const float* __restrict__ beta,
                                                int nrows, float inv_n) {
    int tx = threadIdx.x & 31, ty = threadIdx.x >> 5;
    float4 s = {0.f, 0.f, 0.f, 0.f}, q = {0.f, 0.f, 0.f, 0.f};
    for (int r = blockIdx.x * 8 + ty; r < nrows; r += gridDim.x * 8) {
        float4 v = x4[(size_t)r * 32 + tx];
        s.x += v.x; s.y += v.y; s.z += v.z; s.w += v.w;
        q.x += v.x * v.x; q.y += v.y * v.y; q.z += v.z * v.z; q.w += v.w * v.w;
    }
    __shared__ float4 rs[8][32], rq[8][32];
    __shared__ int slast;
    rs[ty][tx] = s; rq[ty][tx] = q;
    __syncthreads();
    if (ty == 0) {
        for (int w = 1; w < 8; w++) {
            float4 a = rs[w][tx], b = rq[w][tx];
            s.x += a.x; s.y += a.y; s.z += a.z; s.w += a.w;
            q.x += b.x; q.y += b.y; q.z += b.z; q.w += b.w;
        }
        atomicAdd(&g_stats[4 * tx + 0], s.x);
        atomicAdd(&g_stats[4 * tx + 1], s.y);
        atomicAdd(&g_stats[4 * tx + 2], s.z);
        atomicAdd(&g_stats[4 * tx + 3], s.w);
        atomicAdd(&g_stats[D + 4 * tx + 0], q.x);
        atomicAdd(&g_stats[D + 4 * tx + 1], q.y);
        atomicAdd(&g_stats[D + 4 * tx + 2], q.z);
        atomicAdd(&g_stats[D + 4 * tx + 3], q.w);
        __threadfence();
    }
    __syncthreads();
    if (threadIdx.x == 0) {
        int t = atomicAdd(&g_k1done, 1);
        slast = (t == gridDim.x - 1) ? 1 : 0;
    }
    __syncthreads();
    if (slast && threadIdx.x < D) {
        int c = threadIdx.x;
        float ssum = __ldcg(&g_stats[c]);
        float qsum = __ldcg(&g_stats[D + c]);
        float mu  = ssum * inv_n;
        float var = fmaxf(qsum * inv_n - mu * mu, 0.0f);
        float a = gamma[c] * rsqrtf(var + 1e-5f);
        g_ab[c] = a;
        g_ab[D + c] = beta[c] - mu * a;
    }
}

// ---------------- k3: HMMA fp16 single-product GEMM + prefetch ----------------
// smem: Whi(34816) | Xhi(17408) = 52224 B per CTA, 2 CTAs/SM
#define SM_WHI 0
#define SM_XHI 34816
#define SM_TOTAL 52224
#define XSTR 272     // row stride bytes

__global__ void __launch_bounds__(256, 2) k3_mma(const float* __restrict__ x,
                                                 int nrows, int ntiles) {
    extern __shared__ __align__(16) char sm[];
    uint32_t smb = smem_u32(sm);
    int tid = threadIdx.x, wid = tid >> 5, lane = tid & 31;
    int warp_m = wid & 1;       // 2 m-blocks of 32 rows
    int warp_n = wid >> 1;      // 4 n-blocks of 32 cols

    {
        const uint4* hs = (const uint4*)g_Whi;
        uint4* hd = (uint4*)(sm + SM_WHI);
        for (int i = tid; i < 2176; i += 256) hd[i] = hs[i];
    }

    int laneRowA = (lane & 7) + ((lane >> 3) & 1) * 8;
    int laneKA   = (lane >> 4) * 8;
    int laneRowB = (lane & 7) + ((lane >> 4) & 1) * 8;
    int laneKB   = ((lane >> 3) & 1) * 8;
    uint32_t aoff = (uint32_t)((warp_m * 32 + laneRowA) * XSTR + laneKA * 2);
    uint32_t boff = (uint32_t)((warp_n * 32 + laneRowB) * XSTR + laneKB * 2);
    uint32_t a_hi = smb + SM_XHI + aoff;
    uint32_t b_hi = smb + SM_WHI + boff;

    const float4* x4 = (const float4*)x;
    int row_in = tid >> 5;
    int cq = tid & 31;
    float4 aba = ((const float4*)g_ab)[cq];
    float4 abb = ((const float4*)g_ab)[32 + cq];

    // prefetch first tile into regs
    float4 v[8];
    {
        int t0 = blockIdx.x;
        #pragma unroll
        for (int it = 0; it < 8; it++) {
            int gr = t0 * TILE_M + row_in + it * 8;
            v[it] = (t0 < ntiles && gr < nrows) ? x4[(size_t)gr * 32 + cq]
                                                : make_float4(0.f, 0.f, 0.f, 0.f);
        }
    }

    for (int t = blockIdx.x; t < ntiles; t += gridDim.x) {
        // ---- convert regs -> fp16 -> STS ----
        #pragma unroll
        for (int it = 0; it < 8; it++) {
            int r = row_in + it * 8;
            float y0 = fmaxf(fmaf(aba.x, v[it].x, abb.x), 0.f);
            float y1 = fmaxf(fmaf(aba.y, v[it].y, abb.y), 0.f);
            float y2 = fmaxf(fmaf(aba.z, v[it].z, abb.z), 0.f);
            float y3 = fmaxf(fmaf(aba.w, v[it].w, abb.w), 0.f);
            __half2 p01 = __floats2half2_rn(y0, y1);
            __half2 p23 = __floats2half2_rn(y2, y3);
            uint2 hiw;
            hiw.x = *(uint32_t*)&p01;
            hiw.y = *(uint32_t*)&p23;
            uint32_t off = (uint32_t)(r * XSTR + cq * 8);
            *(uint2*)(sm + SM_XHI + off) = hiw;
        }
        __syncthreads();

        // ---- issue prefetch of next tile (hides under MMAs) ----
        {
            int tn = t + gridDim.x;
            #pragma unroll
            for (int it = 0; it < 8; it++) {
                int gr = tn * TILE_M + row_in + it * 8;
                if (tn < ntiles && gr < nrows) v[it] = x4[(size_t)gr * 32 + cq];
                else v[it] = make_float4(0.f, 0.f, 0.f, 0.f);
            }
        }

        // ---- mainloop: 8 k16-steps x 1 product ----
        float acc[2][4][4];
        #pragma unroll
        for (int mt = 0; mt < 2; mt++)
            #pragma unroll
            for (int nt = 0; nt < 4; nt++)
                #pragma unroll
                for (int j = 0; j < 4; j++) acc[mt][nt][j] = 0.f;

        for (int ko = 0; ko < 8; ko++) {
            uint32_t kb = ko * 32;
            uint32_t ah[2][4];
            #pragma unroll
            for (int mt = 0; mt < 2; mt++)
                ldmx4(a_hi + mt * (16 * XSTR) + kb, ah[mt]);
            uint32_t bh[4][2];
            #pragma unroll
            for (int np = 0; np < 2; np++) {
                uint32_t tm[4];
                ldmx4(b_hi + np * (16 * XSTR) + kb, tm);
                bh[2*np][0] = tm[0]; bh[2*np][1] = tm[1];
                bh[2*np+1][0] = tm[2]; bh[2*np+1][1] = tm[3];
            }
            #pragma unroll
            for (int mt = 0; mt < 2; mt++)
                #pragma unroll
                for (int nt = 0; nt < 4; nt++)
                    mma16816h(acc[mt][nt], ah[mt], bh[nt]);
        }

        // ---- epilogue: write h fp16 ----
        int rbase = t * TILE_M + warp_m * 32 + (lane >> 2);
        int cbase = warp_n * 32 + 2 * (lane & 3);
        #pragma unroll
        for (int mt = 0; mt < 2; mt++) {
            #pragma unroll
            for (int nt = 0; nt < 4; nt++) {
                int r0 = rbase + mt * 16;
                int c = cbase + nt * 8;
                if (r0 < nrows) {
                    __half2 p = __floats2half2_rn(acc[mt][nt][0], acc[mt][nt][1]);
                    *(__half2*)&g_h[(size_t)r0 * D + c] = p;
                }
                if (r0 + 8 < nrows) {
                    __half2 p = __floats2half2_rn(acc[mt][nt][2], acc[mt][nt][3]);
                    *(__half2*)&g_h[(size_t)(r0 + 8) * D + c] = p;
                }
            }
        }
        __syncthreads();
    }
}

// ---------------- CSR build ----------------
__global__ void __launch_bounds__(256) k4a_hist(const int* __restrict__ ei, int E) {
    int base = blockIdx.x * 1024 + threadIdx.x;
    #pragma unroll
    for (int j = 0; j < 4; j++) {
        int e = base + j * 256;
        if (e < E) atomicAdd(&g_deg[ei[e]], 1);
    }
}
__global__ void __launch_bounds__(256) k4b_off(int N) {
    int i = blockIdx.x * 256 + threadIdx.x;
    int lane = threadIdx.x & 31;
    int v = (i < N) ? g_deg[i] : 0;
    int incl = v;
    #pragma unroll
    for (int o = 1; o < 32; o <<= 1) {
        int t = __shfl_up_sync(0xFFFFFFFFu, incl, o);
        if (lane >= o) incl += t;
    }
    int wsum = __shfl_sync(0xFFFFFFFFu, incl, 31);
    int base = 0;
    if (lane == 0) base = atomicAdd(&g_total, wsum);
    base = __shfl_sync(0xFFFFFFFFu, base, 0);
    if (i < N) {
        int off = base + incl - v;
        g_off[i] = off;
        g_cur[i] = off;
    }
}
__global__ void __launch_bounds__(256) k4c_fill(const int* __restrict__ ei,
                                                const float* __restrict__ ew, int E) {
    int base = blockIdx.x * 1024 + threadIdx.x;
    int e0 = base, e1 = base + 256, e2 = base + 512, e3 = base + 768;
    int r0 = (e0 < E) ? ei[e0] : -1;
    int r1 = (e1 < E) ? ei[e1] : -1;
    int r2 = (e2 < E) ? ei[e2] : -1;
    int r3 = (e3 < E) ? ei[e3] : -1;
    int p0 = (r0 >= 0) ? atomicAdd(&g_cur[r0], 1) : 0;
    int p1 = (r1 >= 0) ? atomicAdd(&g_cur[r1], 1) : 0;
    int p2 = (r2 >= 0) ? atomicAdd(&g_cur[r2], 1) : 0;
    int p3 = (r3 >= 0) ? atomicAdd(&g_cur[r3], 1) : 0;
    if (r0 >= 0) { g_ecol[p0] = ei[E + e0]; g_ewt[p0] = ew[e0]; }
    if (r1 >= 0) { g_ecol[p1] = ei[E + e1]; g_ewt[p1] = ew[e1]; }
    if (r2 >= 0) { g_ecol[p2] = ei[E + e2]; g_ewt[p2] = ew[e2]; }
    if (r3 >= 0) { g_ecol[p3] = ei[E + e3]; g_ewt[p3] = ew[e3]; }
}

// ---------------- k5: per-node fp16 gather aggregate + h*h (MLP-4) ----------------
__global__ void __launch_bounds__(256) k5_agg(float* __restrict__ out, int N) {
    int n = blockIdx.x * 8 + (threadIdx.x >> 5);
    if (n >= N) return;
    int lane = threadIdx.x & 31;
    int s = g_off[n];
    int e = s + g_deg[n];
    const uint2* h2 = (const uint2*)g_h;      // 8B = 4 halves per lane
    float4 acc = {0.f, 0.f, 0.f, 0.f};
    int j = s;
    for (; j + 4 <= e; j += 4) {
        int c0 = __ldg(&g_ecol[j]),     c1 = __ldg(&g_ecol[j + 1]);
        int c2 = __ldg(&g_ecol[j + 2]), c3 = __ldg(&g_ecol[j + 3]);
        float w0 = __ldg(&g_ewt[j]),     w1 = __ldg(&g_ewt[j + 1]);
        float w2 = __ldg(&g_ewt[j + 2]), w3 = __ldg(&g_ewt[j + 3]);
        uint2 p0 = h2[(size_t)c0 * 32 + lane];
        uint2 p1 = h2[(size_t)c1 * 32 + lane];
        uint2 p2 = h2[(size_t)c2 * 32 + lane];
        uint2 p3 = h2[(size_t)c3 * 32 + lane];
        float2 a0 = __half22float2(*(__half2*)&p0.x), b0 = __half22float2(*(__half2*)&p0.y);
        float2 a1 = __half22float2(*(__half2*)&p1.x), b1 = __half22float2(*(__half2*)&p1.y);
        float2 a2 = __half22float2(*(__half2*)&p2.x), b2 = __half22float2(*(__half2*)&p2.y);
        float2 a3 = __half22float2(*(__half2*)&p3.x), b3 = __half22float2(*(__half2*)&p3.y);
        acc.x = fmaf(w0, a0.x, acc.x); acc.y = fmaf(w0, a0.y, acc.y);
        acc.z = fmaf(w0, b0.x, acc.z); acc.w = fmaf(w0, b0.y, acc.w);
        acc.x = fmaf(w1, a1.x, acc.x); acc.y = fmaf(w1, a1.y, acc.y);
        acc.z = fmaf(w1, b1.x, acc.z); acc.w = fmaf(w1, b1.y, acc.w);
        acc.x = fmaf(w2, a2.x, acc.x); acc.y = fmaf(w2, a2.y, acc.y);
        acc.z = fmaf(w2, b2.x, acc.z); acc.w = fmaf(w2, b2.y, acc.w);
        acc.x = fmaf(w3, a3.x, acc.x); acc.y = fmaf(w3, a3.y, acc.y);
        acc.z = fmaf(w3, b3.x, acc.z); acc.w = fmaf(w3, b3.y, acc.w);
    }
    for (; j < e; j++) {
        int c0 = __ldg(&g_ecol[j]);
        float w0 = __ldg(&g_ewt[j]);
        uint2 p0 = h2[(size_t)c0 * 32 + lane];
        float2 a0 = __half22float2(*(__half2*)&p0.x), b0 = __half22float2(*(__half2*)&p0.y);
        acc.x = fmaf(w0, a0.x, acc.x); acc.y = fmaf(w0, a0.y, acc.y);
        acc.z = fmaf(w0, b0.x, acc.z); acc.w = fmaf(w0, b0.y, acc.w);
    }
    uint2 ph = h2[(size_t)n * 32 + lane];
    float2 ha = __half22float2(*(__half2*)&ph.x), hb = __half22float2(*(__half2*)&ph.y);
    float4 o;
    o.x = fmaf(ha.x, ha.x, acc.x);
    o.y = fmaf(ha.y, ha.y, acc.y);
    o.z = fmaf(hb.x, hb.x, acc.z);
    o.w = fmaf(hb.y, hb.y, acc.w);
    __stcs(&((float4*)out)[(size_t)n * 32 + lane], o);
}

// ---------------- launch: fork CSR chain onto a side stream ----------------
extern "C" void kernel_launch(void* const* d_in, const int* in_sizes, int n_in,
                              void* d_out, int out_size) {
    const float* n_feat = (const float*)d_in[0];
    const int*   ei     = (const int*)d_in[1];
    const float* ew     = (const float*)d_in[2];
    const float* gamma  = (const float*)d_in[3];
    const float* beta   = (const float*)d_in[4];
    const float* W      = (const float*)d_in[5];
    float* out = (float*)d_out;

    int N = in_sizes[0] / D;
    int E = in_sizes[2];
    int ntiles = (N + TILE_M - 1) / TILE_M;

    cudaStream_t s2;
    cudaStreamCreateWithFlags(&s2, cudaStreamNonBlocking);
    cudaEvent_t ev_fork, ev_join;
    cudaEventCreateWithFlags(&ev_fork, cudaEventDisableTiming);
    cudaEventCreateWithFlags(&ev_join, cudaEventDisableTiming);

    k0_prep<<<NB256, 256>>>(W);
    cudaEventRecord(ev_fork, 0);

    cudaStreamWaitEvent(s2, ev_fork, 0);
    k4a_hist<<<(E + 1023) / 1024, 256, 0, s2>>>(ei, E);
    k4b_off<<<(N + 255) / 256, 256, 0, s2>>>(N);
    k4c_fill<<<(E + 1023) / 1024, 256, 0, s2>>>(ei, ew, E);
    cudaEventRecord(ev_join, s2);

    k1_stats<<<264, 256>>>((const float4*)n_feat, gamma, beta, N, 1.0f / (float)N);
    cudaFuncSetAttribute(k3_mma, cudaFuncAttributeMaxDynamicSharedMemorySize, SM_TOTAL);
    k3_mma<<<296, 256, SM_TOTAL>>>(n_feat, N, ntiles);

    cudaStreamWaitEvent(0, ev_join, 0);
    k5_agg<<<(N + 7) / 8, 256>>>(out, N);

    cudaEventDestroy(ev_fork);
    cudaEventDestroy(ev_join);
    cudaStreamDestroy(s2);
}